// round 1
// baseline (speedup 1.0000x reference)
#include <cuda_runtime.h>
#include <cstdint>

#define BB 4
#define NA 211200
#define CC 256
#define HH 200
#define WW 176
#define KK 4096

// Precomputed per-keypoint bilinear params (identical across all channels).
__device__ int4   g_off[BB * KK];
__device__ float4 g_w[BB * KK];

// ---------------------------------------------------------------------------
// Kernel 1: VoxelNet box decode. One thread per box.
// ---------------------------------------------------------------------------
__global__ void decode_kernel(const float* __restrict__ deltas,
                              const float* __restrict__ anchors,
                              float* __restrict__ out) {
    int i = blockIdx.x * blockDim.x + threadIdx.x;
    if (i >= BB * NA) return;
    const float* p = deltas + (size_t)i * 7;
    const float* a = anchors + (size_t)i * 7;
    float p0 = __ldg(p + 0), p1 = __ldg(p + 1), p2 = __ldg(p + 2);
    float p3 = __ldg(p + 3), p4 = __ldg(p + 4), p5 = __ldg(p + 5);
    float p6 = __ldg(p + 6);
    float a0 = __ldg(a + 0), a1 = __ldg(a + 1), a2 = __ldg(a + 2);
    float a3 = __ldg(a + 3), a4 = __ldg(a + 4), a5 = __ldg(a + 5);
    float a6 = __ldg(a + 6);
    float d = sqrtf(a3 * a3 + a4 * a4);
    float* o = out + (size_t)i * 7;
    o[0] = fmaf(p0, d, a0);
    o[1] = fmaf(p1, d, a1);
    o[2] = fmaf(p2, a5, a2);
    o[3] = expf(p3) * a3;
    o[4] = expf(p4) * a4;
    o[5] = expf(p5) * a5;
    o[6] = p6 + a6;
}

// ---------------------------------------------------------------------------
// Kernel 2: per-keypoint bilinear parameter precompute (B*K = 16384 threads).
// Replicates: clamp -> normalize (note divisor dims-2) -> flip -> grid_sample
// align_corners=True with zeros padding.
// ---------------------------------------------------------------------------
__global__ void precomp_kernel(const float* __restrict__ kp) {
    int i = blockIdx.x * blockDim.x + threadIdx.x;
    if (i >= BB * KK) return;
    float kx = __ldg(kp + (size_t)i * 3 + 0);
    float ky = __ldg(kp + (size_t)i * 3 + 1);

    const float inv_px = 1.0f / (0.05f * 8.0f);
    float indx = (kx - 0.0f) * inv_px;      // width-ish pixel index
    float indy = (ky + 40.0f) * inv_px;     // height-ish pixel index
    indx = fminf(fmaxf(indx, 0.0f), (float)(WW - 1));
    indy = fminf(fmaxf(indy, 0.0f), (float)(HH - 1));

    // normalized = 2*(ind/(dims-1-1)) - 1 ; grid = flip -> grid0 from indy,
    // grid1 from indx. Then ix=(g0+1)*0.5*(W-1), iy=(g1+1)*0.5*(H-1).
    float g0 = 2.0f * (indy / (float)(HH - 2)) - 1.0f;
    float g1 = 2.0f * (indx / (float)(WW - 2)) - 1.0f;
    float ix = (g0 + 1.0f) * 0.5f * (float)(WW - 1);
    float iy = (g1 + 1.0f) * 0.5f * (float)(HH - 1);

    float x0f = floorf(ix);
    float y0f = floorf(iy);
    float wx = ix - x0f;
    float wy = iy - y0f;
    int x0 = (int)x0f, y0 = (int)y0f;
    int x1 = x0 + 1, y1 = y0 + 1;

    bool vx0 = (x0 >= 0) && (x0 <= WW - 1);
    bool vx1 = (x1 >= 0) && (x1 <= WW - 1);
    bool vy0 = (y0 >= 0) && (y0 <= HH - 1);
    bool vy1 = (y1 >= 0) && (y1 <= HH - 1);
    int cx0 = min(max(x0, 0), WW - 1);
    int cx1 = min(max(x1, 0), WW - 1);
    int cy0 = min(max(y0, 0), HH - 1);
    int cy1 = min(max(y1, 0), HH - 1);

    int4 off;
    float4 w;
    off.x = cy0 * WW + cx0;  w.x = (vy0 && vx0) ? (1.0f - wx) * (1.0f - wy) : 0.0f;
    off.y = cy0 * WW + cx1;  w.y = (vy0 && vx1) ? wx * (1.0f - wy)          : 0.0f;
    off.z = cy1 * WW + cx0;  w.z = (vy1 && vx0) ? (1.0f - wx) * wy          : 0.0f;
    off.w = cy1 * WW + cx1;  w.w = (vy1 && vx1) ? wx * wy                   : 0.0f;
    g_off[i] = off;
    g_w[i]   = w;
}

// ---------------------------------------------------------------------------
// Kernel 3: bilinear gather. One block per (b, c) channel plane; threads over
// keypoints k -> coalesced writes, all scattered reads stay inside one
// 140.8 KB plane (L1-resident).
// ---------------------------------------------------------------------------
__global__ void __launch_bounds__(256) gather_kernel(
    const float* __restrict__ fm, float* __restrict__ out) {
    int plane = blockIdx.x;                 // = b * C + c
    int b = plane / CC;
    const float* pf = fm + (size_t)plane * (HH * WW);
    float* po = out + (size_t)plane * KK;
    const int4*   offp = g_off + (size_t)b * KK;
    const float4* wp   = g_w   + (size_t)b * KK;

    const int iters = KK / 256;             // 16
#pragma unroll 4
    for (int it = 0; it < iters; ++it) {
        int k = threadIdx.x + it * 256;
        int4 o = __ldg(offp + k);
        float4 w = __ldg(wp + k);
        float v = w.x * __ldg(pf + o.x);
        v = fmaf(w.y, __ldg(pf + o.y), v);
        v = fmaf(w.z, __ldg(pf + o.z), v);
        v = fmaf(w.w, __ldg(pf + o.w), v);
        po[k] = v;
    }
}

// ---------------------------------------------------------------------------
extern "C" void kernel_launch(void* const* d_in, const int* in_sizes, int n_in,
                              void* d_out, int out_size) {
    const float* deltas  = (const float*)d_in[0];
    const float* anchors = (const float*)d_in[1];
    const float* fm      = (const float*)d_in[2];
    const float* kp      = (const float*)d_in[3];
    float* out = (float*)d_out;

    // Output layout: boxes (B, NA, 7) followed by bev_features (B, C, K).
    float* out_boxes = out;
    float* out_feats = out + (size_t)BB * NA * 7;

    decode_kernel<<<(BB * NA + 255) / 256, 256>>>(deltas, anchors, out_boxes);
    precomp_kernel<<<(BB * KK + 255) / 256, 256>>>(kp);
    gather_kernel<<<BB * CC, 256>>>(fm, out_feats);
}

// round 3
// speedup vs baseline: 1.3793x; 1.3793x over previous
#include <cuda_runtime.h>
#include <cstdint>

#define BB 4
#define NA 211200
#define CC 256
#define HH 200
#define WW 176
#define KK 4096
#define PLANE (HH * WW)            // 35200 floats = 140800 bytes

// Precomputed per-keypoint bilinear params (identical across all channels).
__device__ int4   g_off[BB * KK];
__device__ float4 g_w[BB * KK];

// ---------------------------------------------------------------------------
// Kernel 1: VoxelNet box decode, fully coalesced via smem staging.
// 256 boxes per block = 1792 floats per array = 448 float4.
// ---------------------------------------------------------------------------
__global__ void __launch_bounds__(256) decode_kernel(
    const float* __restrict__ deltas,
    const float* __restrict__ anchors,
    float* __restrict__ out) {
    __shared__ float sp[1792];
    __shared__ float sa[1792];
    __shared__ float so[1792];

    size_t base = (size_t)blockIdx.x * 1792;
    const float4* dp = (const float4*)(deltas + base);
    const float4* ap = (const float4*)(anchors + base);
    float4* op = (float4*)(out + base);

    int t = threadIdx.x;
    // 448 float4 each, 256 threads -> 2 iterations (partial second).
    {
        float4 v = dp[t];
        ((float4*)sp)[t] = v;
        float4 w = ap[t];
        ((float4*)sa)[t] = w;
        int t2 = t + 256;
        if (t2 < 448) {
            ((float4*)sp)[t2] = dp[t2];
            ((float4*)sa)[t2] = ap[t2];
        }
    }
    __syncthreads();

    {
        const float* p = sp + t * 7;
        const float* a = sa + t * 7;
        float p0 = p[0], p1 = p[1], p2 = p[2], p3 = p[3], p4 = p[4], p5 = p[5], p6 = p[6];
        float a0 = a[0], a1 = a[1], a2 = a[2], a3 = a[3], a4 = a[4], a5 = a[5], a6 = a[6];
        float d = sqrtf(a3 * a3 + a4 * a4);
        float* o = so + t * 7;
        o[0] = fmaf(p0, d, a0);
        o[1] = fmaf(p1, d, a1);
        o[2] = fmaf(p2, a5, a2);
        o[3] = expf(p3) * a3;
        o[4] = expf(p4) * a4;
        o[5] = expf(p5) * a5;
        o[6] = p6 + a6;
    }
    __syncthreads();

    {
        op[t] = ((float4*)so)[t];
        int t2 = t + 256;
        if (t2 < 448) op[t2] = ((float4*)so)[t2];
    }
}

// ---------------------------------------------------------------------------
// Kernel 2: per-keypoint bilinear parameter precompute (B*K = 16384 threads).
// Replicates: clamp -> normalize (divisor dims-2 quirk) -> flip -> grid_sample
// align_corners=True with zeros padding.
// ---------------------------------------------------------------------------
__global__ void precomp_kernel(const float* __restrict__ kp) {
    int i = blockIdx.x * blockDim.x + threadIdx.x;
    if (i >= BB * KK) return;
    float kx = __ldg(kp + (size_t)i * 3 + 0);
    float ky = __ldg(kp + (size_t)i * 3 + 1);

    const float inv_px = 1.0f / (0.05f * 8.0f);
    float indx = (kx - 0.0f) * inv_px;
    float indy = (ky + 40.0f) * inv_px;
    indx = fminf(fmaxf(indx, 0.0f), (float)(WW - 1));
    indy = fminf(fmaxf(indy, 0.0f), (float)(HH - 1));

    float g0 = 2.0f * (indy / (float)(HH - 2)) - 1.0f;
    float g1 = 2.0f * (indx / (float)(WW - 2)) - 1.0f;
    float ix = (g0 + 1.0f) * 0.5f * (float)(WW - 1);
    float iy = (g1 + 1.0f) * 0.5f * (float)(HH - 1);

    float x0f = floorf(ix);
    float y0f = floorf(iy);
    float wx = ix - x0f;
    float wy = iy - y0f;
    int x0 = (int)x0f, y0 = (int)y0f;
    int x1 = x0 + 1, y1 = y0 + 1;

    bool vx0 = (x0 >= 0) && (x0 <= WW - 1);
    bool vx1 = (x1 >= 0) && (x1 <= WW - 1);
    bool vy0 = (y0 >= 0) && (y0 <= HH - 1);
    bool vy1 = (y1 >= 0) && (y1 <= HH - 1);
    int cx0 = min(max(x0, 0), WW - 1);
    int cx1 = min(max(x1, 0), WW - 1);
    int cy0 = min(max(y0, 0), HH - 1);
    int cy1 = min(max(y1, 0), HH - 1);

    int4 off;
    float4 w;
    off.x = cy0 * WW + cx0;  w.x = (vy0 && vx0) ? (1.0f - wx) * (1.0f - wy) : 0.0f;
    off.y = cy0 * WW + cx1;  w.y = (vy0 && vx1) ? wx * (1.0f - wy)          : 0.0f;
    off.z = cy1 * WW + cx0;  w.z = (vy1 && vx0) ? (1.0f - wx) * wy          : 0.0f;
    off.w = cy1 * WW + cx1;  w.w = (vy1 && vx1) ? wx * wy                   : 0.0f;
    g_off[i] = off;
    g_w[i]   = w;
}

// ---------------------------------------------------------------------------
// Kernel 3: bilinear gather, plane staged in shared memory.
// One CTA per (b, c) plane: coalesced float4 load of the 140.8 KB plane into
// dynamic smem, then scattered reads hit the smem crossbar (~3 cyc conflict
// degree) instead of generating 32 L1 wavefronts per warp-load.
// ---------------------------------------------------------------------------
__global__ void __launch_bounds__(512) gather_kernel(
    const float* __restrict__ fm, float* __restrict__ out) {
    extern __shared__ float splane[];

    int c = blockIdx.x;
    int b = blockIdx.y;
    int plane = b * CC + c;
    const float4* pf4 = (const float4*)(fm + (size_t)plane * PLANE);
    float* po = out + (size_t)plane * KK;
    const int4*   offp = g_off + (size_t)b * KK;
    const float4* wp   = g_w   + (size_t)b * KK;

    // Stage plane: 35200 floats = 8800 float4.
    float4* s4 = (float4*)splane;
#pragma unroll
    for (int i = threadIdx.x; i < PLANE / 4; i += 512) {
        s4[i] = pf4[i];
    }
    __syncthreads();

    // Gather: 4096 keypoints, 512 threads -> 8 per thread, coalesced I/O.
#pragma unroll
    for (int it = 0; it < KK / 512; ++it) {
        int k = threadIdx.x + it * 512;
        int4 o = __ldg(offp + k);
        float4 w = __ldg(wp + k);
        float v = w.x * splane[o.x];
        v = fmaf(w.y, splane[o.y], v);
        v = fmaf(w.z, splane[o.z], v);
        v = fmaf(w.w, splane[o.w], v);
        po[k] = v;
    }
}

// ---------------------------------------------------------------------------
extern "C" void kernel_launch(void* const* d_in, const int* in_sizes, int n_in,
                              void* d_out, int out_size) {
    const float* deltas  = (const float*)d_in[0];
    const float* anchors = (const float*)d_in[1];
    const float* fm      = (const float*)d_in[2];
    const float* kp      = (const float*)d_in[3];
    float* out = (float*)d_out;

    float* out_boxes = out;
    float* out_feats = out + (size_t)BB * NA * 7;

    cudaFuncSetAttribute(gather_kernel,
                         cudaFuncAttributeMaxDynamicSharedMemorySize,
                         PLANE * sizeof(float));

    decode_kernel<<<BB * NA / 256, 256>>>(deltas, anchors, out_boxes);
    precomp_kernel<<<(BB * KK + 255) / 256, 256>>>(kp);
    gather_kernel<<<dim3(CC, BB), 512, PLANE * sizeof(float)>>>(fm, out_feats);
}

// round 4
// speedup vs baseline: 1.6590x; 1.2028x over previous
#include <cuda_runtime.h>
#include <cuda_fp16.h>
#include <cstdint>

#define BB 4
#define NA 211200
#define CC 256
#define HH 200
#define WW 176
#define KK 4096
#define PLANE (HH * WW)            // 35200 floats

#define GATHER_BLOCKS (BB * CC)    // 1024
#define DEC_BOX_PER_BLK 512
#define DEC_BLOCKS (BB * NA / DEC_BOX_PER_BLK)  // 1650
#define SMEM_BYTES (PLANE * 2)     // 70400 B (fp16 plane) >= 43008 B decode scratch

// Precomputed per-keypoint bilinear params (identical across all channels).
__device__ int4   g_off[BB * KK];
__device__ float4 g_w[BB * KK];

// ---------------------------------------------------------------------------
// Kernel 1: per-keypoint bilinear parameter precompute (B*K = 16384 threads).
// Replicates: clamp -> normalize (divisor dims-2 quirk) -> flip -> grid_sample
// align_corners=True with zeros padding.
// ---------------------------------------------------------------------------
__global__ void precomp_kernel(const float* __restrict__ kp) {
    int i = blockIdx.x * blockDim.x + threadIdx.x;
    if (i >= BB * KK) return;
    float kx = __ldg(kp + (size_t)i * 3 + 0);
    float ky = __ldg(kp + (size_t)i * 3 + 1);

    const float inv_px = 1.0f / (0.05f * 8.0f);
    float indx = kx * inv_px;
    float indy = (ky + 40.0f) * inv_px;
    indx = fminf(fmaxf(indx, 0.0f), (float)(WW - 1));
    indy = fminf(fmaxf(indy, 0.0f), (float)(HH - 1));

    float g0 = 2.0f * (indy / (float)(HH - 2)) - 1.0f;
    float g1 = 2.0f * (indx / (float)(WW - 2)) - 1.0f;
    float ix = (g0 + 1.0f) * 0.5f * (float)(WW - 1);
    float iy = (g1 + 1.0f) * 0.5f * (float)(HH - 1);

    float x0f = floorf(ix);
    float y0f = floorf(iy);
    float wx = ix - x0f;
    float wy = iy - y0f;
    int x0 = (int)x0f, y0 = (int)y0f;
    int x1 = x0 + 1, y1 = y0 + 1;

    bool vx0 = (x0 >= 0) && (x0 <= WW - 1);
    bool vx1 = (x1 >= 0) && (x1 <= WW - 1);
    bool vy0 = (y0 >= 0) && (y0 <= HH - 1);
    bool vy1 = (y1 >= 0) && (y1 <= HH - 1);
    int cx0 = min(max(x0, 0), WW - 1);
    int cx1 = min(max(x1, 0), WW - 1);
    int cy0 = min(max(y0, 0), HH - 1);
    int cy1 = min(max(y1, 0), HH - 1);

    int4 off;
    float4 w;
    off.x = cy0 * WW + cx0;  w.x = (vy0 && vx0) ? (1.0f - wx) * (1.0f - wy) : 0.0f;
    off.y = cy0 * WW + cx1;  w.y = (vy0 && vx1) ? wx * (1.0f - wy)          : 0.0f;
    off.z = cy1 * WW + cx0;  w.z = (vy1 && vx0) ? (1.0f - wx) * wy          : 0.0f;
    off.w = cy1 * WW + cx1;  w.w = (vy1 && vx1) ? wx * wy                   : 0.0f;
    g_off[i] = off;
    g_w[i]   = w;
}

// ---------------------------------------------------------------------------
// Kernel 2: FUSED gather + decode. Gather blocks [0, 1024): one (b,c) plane
// each, staged as fp16 in 70.4 KB smem (3 CTAs/SM -> phases overlap across
// CTAs). Decode blocks [1024, 1024+1650): coalesced smem-staged box decode
// reusing the same dynamic smem as fp32 scratch. Both are DRAM streams; the
// fusion lets them share the HBM pipe instead of serializing.
// ---------------------------------------------------------------------------
__global__ void __launch_bounds__(512) fused_kernel(
    const float* __restrict__ fm,
    const float* __restrict__ deltas,
    const float* __restrict__ anchors,
    float* __restrict__ out_feats,
    float* __restrict__ out_boxes) {
    extern __shared__ char smem_raw[];

    if (blockIdx.x < GATHER_BLOCKS) {
        // ------------------------- gather branch --------------------------
        __half* splane = (__half*)smem_raw;
        int plane = blockIdx.x;               // = b * CC + c
        int b = plane / CC;
        const float4* pf4 = (const float4*)(fm + (size_t)plane * PLANE);
        float* po = out_feats + (size_t)plane * KK;
        const int4*   offp = g_off + (size_t)b * KK;
        const float4* wp   = g_w   + (size_t)b * KK;

        // Stage plane as fp16: 8800 float4 -> 8800 half2-pairs.
        __half2* s2 = (__half2*)splane;
#pragma unroll
        for (int i = threadIdx.x; i < PLANE / 4; i += 512) {
            float4 v = pf4[i];
            s2[i * 2 + 0] = __floats2half2_rn(v.x, v.y);
            s2[i * 2 + 1] = __floats2half2_rn(v.z, v.w);
        }
        __syncthreads();

        // Gather: 4096 keypoints, 8 per thread, coalesced param reads + store.
#pragma unroll
        for (int it = 0; it < KK / 512; ++it) {
            int k = threadIdx.x + it * 512;
            int4 o = __ldg(offp + k);
            float4 w = __ldg(wp + k);
            float v = w.x * __half2float(splane[o.x]);
            v = fmaf(w.y, __half2float(splane[o.y]), v);
            v = fmaf(w.z, __half2float(splane[o.z]), v);
            v = fmaf(w.w, __half2float(splane[o.w]), v);
            po[k] = v;
        }
    } else {
        // ------------------------- decode branch --------------------------
        // 512 boxes per block = 3584 floats per array = 896 float4.
        float* sp = (float*)smem_raw;            // 3584 floats
        float* sa = sp + 3584;                   // 3584 floats
        float* so = sa + 3584;                   // 3584 floats (total 43008 B)

        int blk = blockIdx.x - GATHER_BLOCKS;
        size_t base = (size_t)blk * (DEC_BOX_PER_BLK * 7);
        const float4* dp = (const float4*)(deltas + base);
        const float4* ap = (const float4*)(anchors + base);
        float4* op = (float4*)(out_boxes + base);

        int t = threadIdx.x;
        {
            ((float4*)sp)[t] = dp[t];
            ((float4*)sa)[t] = ap[t];
            int t2 = t + 512;
            if (t2 < 896) {
                ((float4*)sp)[t2] = dp[t2];
                ((float4*)sa)[t2] = ap[t2];
            }
        }
        __syncthreads();

        {
            const float* p = sp + t * 7;
            const float* a = sa + t * 7;
            float p0 = p[0], p1 = p[1], p2 = p[2], p3 = p[3], p4 = p[4], p5 = p[5], p6 = p[6];
            float a0 = a[0], a1 = a[1], a2 = a[2], a3 = a[3], a4 = a[4], a5 = a[5], a6 = a[6];
            float d = sqrtf(a3 * a3 + a4 * a4);
            float* o = so + t * 7;
            o[0] = fmaf(p0, d, a0);
            o[1] = fmaf(p1, d, a1);
            o[2] = fmaf(p2, a5, a2);
            o[3] = expf(p3) * a3;
            o[4] = expf(p4) * a4;
            o[5] = expf(p5) * a5;
            o[6] = p6 + a6;
        }
        __syncthreads();

        {
            op[t] = ((float4*)so)[t];
            int t2 = t + 512;
            if (t2 < 896) op[t2] = ((float4*)so)[t2];
        }
    }
}

// ---------------------------------------------------------------------------
extern "C" void kernel_launch(void* const* d_in, const int* in_sizes, int n_in,
                              void* d_out, int out_size) {
    const float* deltas  = (const float*)d_in[0];
    const float* anchors = (const float*)d_in[1];
    const float* fm      = (const float*)d_in[2];
    const float* kp      = (const float*)d_in[3];
    float* out = (float*)d_out;

    float* out_boxes = out;
    float* out_feats = out + (size_t)BB * NA * 7;

    cudaFuncSetAttribute(fused_kernel,
                         cudaFuncAttributeMaxDynamicSharedMemorySize,
                         SMEM_BYTES);

    precomp_kernel<<<(BB * KK + 255) / 256, 256>>>(kp);
    fused_kernel<<<GATHER_BLOCKS + DEC_BLOCKS, 512, SMEM_BYTES>>>(
        fm, deltas, anchors, out_feats, out_boxes);
}